// round 1
// baseline (speedup 1.0000x reference)
#include <cuda_runtime.h>

// ---------------- problem constants ----------------
#define N_IMG 2
#define A_ 9
#define C_ 80
#define H_ 100
#define W_ 152
#define HW_ 15200           // H*W
#define CHW_ (C_*HW_)       // 1,216,000
#define ACHW 10944000       // A*C*H*W per image
#define REG_PER_IMG (A_*4*HW_)
#define TOPN 1000
#define POSTN 100
#define CAP 16384
#define NBINS 4096
#define THRESH_LOGIT -2.9444389791664403f   // log(0.05/0.95)
#define BBOX_CLIP 4.1351665567423556f       // log(1000/16)
#define IMW1 1215.0f
#define IMH1 799.0f
#define NMS_T 0.5f

// ---------------- device scratch (static, no allocs) ----------------
__device__ unsigned            g_hist[N_IMG][NBINS];
__device__ int                 g_count[N_IMG];
__device__ int                 g_pivot[N_IMG];
__device__ unsigned long long  g_cand[N_IMG][CAP];
__device__ unsigned long long  g_topkeys[N_IMG][TOPN];
__device__ float               g_boxes[N_IMG][TOPN][4];
__device__ float               g_scores[N_IMG][TOPN];
__device__ int                 g_labels[N_IMG][TOPN];
__device__ unsigned char       g_valid[N_IMG][TOPN];
__device__ unsigned            g_iou[N_IMG][TOPN][32];

// monotone mapping: float bits -> unsigned preserving > ordering
__device__ __forceinline__ unsigned mono_of(float x) {
    unsigned b = __float_as_uint(x);
    return b ^ ((unsigned)((int)b >> 31) | 0x80000000u);
}

// ---------------- 0: zero per-replay state ----------------
__global__ void zero_kernel() {
    int t = blockIdx.x * blockDim.x + threadIdx.x;
    if (t < N_IMG * NBINS) ((unsigned*)g_hist)[t] = 0u;
    if (t < N_IMG) g_count[t] = 0;
}

// ---------------- 1: histogram of monotone keys (above threshold) ----------------
__global__ void hist_kernel(const float* __restrict__ cls) {
    __shared__ unsigned sh[NBINS];
    for (int i = threadIdx.x; i < NBINS; i += blockDim.x) sh[i] = 0u;
    __syncthreads();
    const int n = blockIdx.y;
    const float4* p = reinterpret_cast<const float4*>(cls + (size_t)n * ACHW);
    const int total4 = ACHW / 4;
    for (int i = blockIdx.x * blockDim.x + threadIdx.x; i < total4;
         i += gridDim.x * blockDim.x) {
        float4 v = p[i];
        float vals[4] = {v.x, v.y, v.z, v.w};
#pragma unroll
        for (int e = 0; e < 4; e++) {
            if (vals[e] > THRESH_LOGIT) {
                atomicAdd(&sh[mono_of(vals[e]) >> 20], 1u);
            }
        }
    }
    __syncthreads();
    for (int i = threadIdx.x; i < NBINS; i += blockDim.x) {
        unsigned v = sh[i];
        if (v) atomicAdd(&g_hist[n][i], v);
    }
}

// ---------------- 2: find pivot bucket (cum-from-top >= TOPN) ----------------
__global__ void pivot_kernel() {
    __shared__ unsigned cs[1024];
    __shared__ int s_min;
    const int t = threadIdx.x;
    for (int n = 0; n < N_IMG; n++) {
        if (t == 0) s_min = NBINS;  // sentinel: not found
        __syncthreads();
        unsigned local[4];
        unsigned sum = 0;
#pragma unroll
        for (int e = 0; e < 4; e++) {
            int r = t * 4 + e;                       // reversed position
            unsigned v = g_hist[n][NBINS - 1 - r];
            local[e] = v; sum += v;
        }
        cs[t] = sum;
        __syncthreads();
        for (int off = 1; off < 1024; off <<= 1) {
            unsigned v = (t >= off) ? cs[t - off] : 0u;
            __syncthreads();
            cs[t] += v;
            __syncthreads();
        }
        unsigned run = (t == 0) ? 0u : cs[t - 1];
        int found = -1;
#pragma unroll
        for (int e = 0; e < 4; e++) {
            run += local[e];
            if (found < 0 && run >= TOPN) found = t * 4 + e;
        }
        if (found >= 0) atomicMin(&s_min, found);
        __syncthreads();
        if (t == 0) g_pivot[n] = (s_min >= NBINS) ? 0 : (NBINS - 1 - s_min);
        __syncthreads();
    }
}

// ---------------- 3: collect candidates with mono >= pivot_base ----------------
__global__ void collect_kernel(const float* __restrict__ cls) {
    const int n = blockIdx.y;
    const unsigned pivot_base = (unsigned)g_pivot[n] << 20;
    const float4* p = reinterpret_cast<const float4*>(cls + (size_t)n * ACHW);
    const int total4 = ACHW / 4;
    for (int i = blockIdx.x * blockDim.x + threadIdx.x; i < total4;
         i += gridDim.x * blockDim.x) {
        float4 v = p[i];
        float vals[4] = {v.x, v.y, v.z, v.w};
#pragma unroll
        for (int e = 0; e < 4; e++) {
            float x = vals[e];
            if (x > THRESH_LOGIT) {
                unsigned mono = mono_of(x);
                if (mono >= pivot_base) {
                    int m   = i * 4 + e;             // memory-layout flat index
                    int a   = m / CHW_;
                    int rem = m - a * CHW_;
                    int c   = rem / HW_;
                    int hw  = rem - c * HW_;
                    unsigned ref_idx = (unsigned)((hw * A_ + a) * C_ + c);
                    int pos = atomicAdd(&g_count[n], 1);
                    if (pos < CAP)
                        g_cand[n][pos] =
                            ((unsigned long long)mono << 32) | (0xFFFFFFFFu - ref_idx);
                }
            }
        }
    }
}

// ---------------- 4: bitonic sort candidates desc, emit top-1000 keys ----------------
__global__ void sort_kernel() {
    extern __shared__ unsigned long long sk[];
    const int n = blockIdx.x;
    int cnt = g_count[n];
    if (cnt > CAP) cnt = CAP;
    int m = 1024;
    while (m < cnt) m <<= 1;
    for (int i = threadIdx.x; i < m; i += blockDim.x)
        sk[i] = (i < cnt) ? g_cand[n][i] : 0ULL;
    __syncthreads();
    for (int k = 2; k <= m; k <<= 1) {
        for (int j = k >> 1; j > 0; j >>= 1) {
            for (int i = threadIdx.x; i < m; i += blockDim.x) {
                int ixj = i ^ j;
                if (ixj > i) {
                    unsigned long long va = sk[i], vb = sk[ixj];
                    bool desc = ((i & k) == 0);
                    if (desc ? (va < vb) : (va > vb)) { sk[i] = vb; sk[ixj] = va; }
                }
            }
            __syncthreads();
        }
    }
    for (int i = threadIdx.x; i < TOPN; i += blockDim.x)
        g_topkeys[n][i] = (i < cnt) ? sk[i] : 0ULL;
}

// ---------------- 5: decode boxes for top-1000 ----------------
__global__ void decode_kernel(const float* __restrict__ reg,
                              const float* __restrict__ anchors) {
    const int n = blockIdx.y;
    const int r = blockIdx.x * blockDim.x + threadIdx.x;
    if (r >= TOPN) return;
    unsigned long long key = g_topkeys[n][r];
    if (key == 0ULL) {
        g_scores[n][r] = -1.0f;
        g_valid[n][r] = 0;
        g_labels[n][r] = 0;
        g_boxes[n][r][0] = 0.f; g_boxes[n][r][1] = 0.f;
        g_boxes[n][r][2] = 0.f; g_boxes[n][r][3] = 0.f;
        return;
    }
    unsigned mono = (unsigned)(key >> 32);
    unsigned bits = (mono & 0x80000000u) ? (mono ^ 0x80000000u) : ~mono;
    float logit = __uint_as_float(bits);
    float score = 1.0f / (1.0f + expf(-logit));

    unsigned ref_idx = 0xFFFFFFFFu - (unsigned)(key & 0xFFFFFFFFull);
    int c   = (int)(ref_idx % C_);
    int loc = (int)(ref_idx / C_);
    int a   = loc % A_;
    int hw  = loc / A_;

    const float* anc = anchors + 4 * (size_t)loc;
    float ax1 = anc[0], ay1 = anc[1], ax2 = anc[2], ay2 = anc[3];
    float wdt = ax2 - ax1 + 1.0f;
    float hgt = ay2 - ay1 + 1.0f;
    float ctrx = ax1 + 0.5f * wdt;
    float ctry = ay1 + 0.5f * hgt;

    size_t rb = (size_t)n * REG_PER_IMG + (size_t)a * 4 * HW_ + hw;
    float dx = reg[rb]            / 10.0f;
    float dy = reg[rb + HW_]      / 10.0f;
    float dw = fminf(reg[rb + 2 * HW_] / 5.0f, BBOX_CLIP);
    float dh = fminf(reg[rb + 3 * HW_] / 5.0f, BBOX_CLIP);

    float pcx = dx * wdt + ctrx;
    float pcy = dy * hgt + ctry;
    float pw  = expf(dw) * wdt;
    float ph  = expf(dh) * hgt;

    float x1 = pcx - 0.5f * pw;
    float y1 = pcy - 0.5f * ph;
    float x2 = pcx + 0.5f * pw - 1.0f;
    float y2 = pcy + 0.5f * ph - 1.0f;
    x1 = fminf(fmaxf(x1, 0.0f), IMW1);
    y1 = fminf(fmaxf(y1, 0.0f), IMH1);
    x2 = fminf(fmaxf(x2, 0.0f), IMW1);
    y2 = fminf(fmaxf(y2, 0.0f), IMH1);

    bool valid = (score > 0.0f) &&
                 (x2 - x1 + 1.0f >= 0.0f) &&
                 (y2 - y1 + 1.0f >= 0.0f);

    g_boxes[n][r][0] = x1; g_boxes[n][r][1] = y1;
    g_boxes[n][r][2] = x2; g_boxes[n][r][3] = y2;
    g_scores[n][r] = score;
    g_labels[n][r] = c + 1;
    g_valid[n][r] = valid ? 1 : 0;
}

// ---------------- 6: IoU > 0.5 bitmask (class-offset boxes) ----------------
__global__ void iou_kernel() {
    const int lane = threadIdx.x;                       // 0..31 -> j within word
    const int i    = blockIdx.x * blockDim.y + threadIdx.y;
    const int word = blockIdx.y;
    const int n    = blockIdx.z;
    if (i >= TOPN) return;
    int j  = word * 32 + lane;
    int jc = (j < TOPN) ? j : (TOPN - 1);

    float oi  = (float)g_labels[n][i]  * 4096.0f;
    float oj  = (float)g_labels[n][jc] * 4096.0f;
    float xi1 = g_boxes[n][i][0]  + oi, yi1 = g_boxes[n][i][1]  + oi;
    float xi2 = g_boxes[n][i][2]  + oi, yi2 = g_boxes[n][i][3]  + oi;
    float xj1 = g_boxes[n][jc][0] + oj, yj1 = g_boxes[n][jc][1] + oj;
    float xj2 = g_boxes[n][jc][2] + oj, yj2 = g_boxes[n][jc][3] + oj;

    float ai = (xi2 - xi1 + 1.0f) * (yi2 - yi1 + 1.0f);
    float aj = (xj2 - xj1 + 1.0f) * (yj2 - yj1 + 1.0f);
    float iw = fmaxf(fminf(xi2, xj2) - fmaxf(xi1, xj1) + 1.0f, 0.0f);
    float ih = fmaxf(fminf(yi2, yj2) - fmaxf(yi1, yj1) + 1.0f, 0.0f);
    float inter = iw * ih;
    float iou = inter / (ai + aj - inter);
    bool cond = (j < TOPN) && (iou > NMS_T);
    unsigned bal = __ballot_sync(0xffffffffu, cond);
    if (lane == 0) g_iou[n][i][word] = bal;
}

// ---------------- 7: sequential NMS scan + final top-100 emit ----------------
__global__ void nms_final_kernel(float* __restrict__ out) {
    extern __shared__ unsigned shm[];
    unsigned*      smask = shm;                                  // TOPN*32 words
    float*         ssc   = (float*)(smask + TOPN * 32);          // TOPN
    unsigned char* sval  = (unsigned char*)(ssc + TOPN);         // TOPN
    unsigned char* skeep = sval + TOPN;                          // TOPN
    __shared__ int s_warpoff[32];
    __shared__ int s_totkept;

    const int n = blockIdx.x;
    const int tid = threadIdx.x;

    for (int i = tid; i < TOPN * 32; i += blockDim.x)
        smask[i] = ((const unsigned*)g_iou[n])[i];
    for (int i = tid; i < TOPN; i += blockDim.x) {
        ssc[i]  = g_scores[n][i];
        sval[i] = g_valid[n][i];
    }
    __syncthreads();

    // sequential greedy scan, one warp; lane l owns suppression word l
    if (tid < 32) {
        unsigned supp = 0;
        for (int i = 0; i < TOPN; i++) {
            unsigned sw = __shfl_sync(0xffffffffu, supp, i >> 5);
            bool ki = sval[i] && !((sw >> (i & 31)) & 1u);
            if (ki) supp |= smask[i * 32 + tid];
            if (tid == 0) skeep[i] = ki ? 1 : 0;
        }
    }
    __syncthreads();

    // parallel ranking: kept (in order), then non-kept (in order)
    const int lane = tid & 31, w = tid >> 5;
    const bool in = tid < TOPN;
    int k = (in && skeep[tid]) ? 1 : 0;
    unsigned wb = __ballot_sync(0xffffffffu, k);
    int pre = __popc(wb & ((1u << lane) - 1u));
    if (lane == 0) s_warpoff[w] = __popc(wb);
    __syncthreads();
    if (tid == 0) {
        int s = 0;
        for (int x = 0; x < 32; x++) { int t = s_warpoff[x]; s_warpoff[x] = s; s += t; }
        s_totkept = s;
    }
    __syncthreads();

    if (in) {
        int kept_before = s_warpoff[w] + pre;   // exclusive count of kept in [0,tid)
        int r = k ? kept_before : (s_totkept + (tid - kept_before));
        if (r < POSTN) {
            int base_b = n * POSTN * 4;
            int base_s = N_IMG * POSTN * 4 + n * POSTN;
            int base_l = N_IMG * POSTN * 5 + n * POSTN;
            out[base_b + r * 4 + 0] = g_boxes[n][tid][0];
            out[base_b + r * 4 + 1] = g_boxes[n][tid][1];
            out[base_b + r * 4 + 2] = g_boxes[n][tid][2];
            out[base_b + r * 4 + 3] = g_boxes[n][tid][3];
            out[base_s + r] = k ? ssc[tid] : -1.0f;
            out[base_l + r] = k ? (float)g_labels[n][tid] : 0.0f;
        }
    }
}

// ---------------- host launch ----------------
extern "C" void kernel_launch(void* const* d_in, const int* in_sizes, int n_in,
                              void* d_out, int out_size) {
    (void)in_sizes; (void)n_in; (void)out_size;
    const float* box_cls = (const float*)d_in[0];
    const float* box_reg = (const float*)d_in[1];
    const float* anchors = (const float*)d_in[2];
    float* out = (float*)d_out;

    static bool attr_done = false;
    if (!attr_done) {
        cudaFuncSetAttribute(sort_kernel,
            cudaFuncAttributeMaxDynamicSharedMemorySize, CAP * 8);
        cudaFuncSetAttribute(nms_final_kernel,
            cudaFuncAttributeMaxDynamicSharedMemorySize,
            TOPN * 32 * 4 + TOPN * 4 + 2 * TOPN);
        attr_done = true;
    }

    zero_kernel<<<(N_IMG * NBINS + 255) / 256, 256>>>();
    hist_kernel<<<dim3(96, N_IMG), 1024>>>(box_cls);
    pivot_kernel<<<1, 1024>>>();
    collect_kernel<<<dim3(96, N_IMG), 1024>>>(box_cls);
    sort_kernel<<<N_IMG, 1024, CAP * 8>>>();
    decode_kernel<<<dim3(1, N_IMG), 1024>>>(box_reg, anchors);
    iou_kernel<<<dim3(125, 32, N_IMG), dim3(32, 8)>>>();
    nms_final_kernel<<<N_IMG, 1024, TOPN * 32 * 4 + TOPN * 4 + 2 * TOPN>>>(out);
}